// round 13
// baseline (speedup 1.0000x reference)
#include <cuda_runtime.h>
#include <cuda_fp16.h>
#include <cstdint>

#define S_LEN 4096
#define DM 1024
#define NH 16
#define HD 64
#define NEG_INF __int_as_float(0xff800000)
#define ONES2 0x3C003C00u   // half2 {1.0, 1.0}

// Scratch (device globals: allocation-free per harness rules). All fp16.
__device__ __half g_Q[NH * S_LEN * HD];  // [h][s][d], pre-scaled 0.125*log2(e)
__device__ __half g_K[NH * S_LEN * HD];
__device__ __half g_V[NH * S_LEN * HD];
__device__ __half g_O[S_LEN * DM];       // [s][h*64+d]
__device__ __half g_Xr[S_LEN * DM];      // x in fp16
__device__ __half g_Wr[4][DM * DM];      // W^T: [n][k], k contiguous

__device__ __forceinline__ void mma_f16(float& d0, float& d1, float& d2, float& d3,
                                        unsigned a0, unsigned a1, unsigned a2, unsigned a3,
                                        unsigned b0, unsigned b1) {
    asm volatile(
        "mma.sync.aligned.m16n8k16.row.col.f32.f16.f16.f32 "
        "{%0,%1,%2,%3}, {%4,%5,%6,%7}, {%8,%9}, {%0,%1,%2,%3};"
        : "+f"(d0), "+f"(d1), "+f"(d2), "+f"(d3)
        : "r"(a0), "r"(a1), "r"(a2), "r"(a3), "r"(b0), "r"(b1));
}

__device__ __forceinline__ void ldm_x4(unsigned& r0, unsigned& r1, unsigned& r2,
                                       unsigned& r3, unsigned addr) {
    asm volatile("ldmatrix.sync.aligned.m8n8.x4.shared.b16 {%0,%1,%2,%3}, [%4];"
                 : "=r"(r0), "=r"(r1), "=r"(r2), "=r"(r3) : "r"(addr));
}

__device__ __forceinline__ void cp16(void* smem_dst, const void* gsrc) {
    unsigned d = (unsigned)__cvta_generic_to_shared(smem_dst);
    asm volatile("cp.async.cg.shared.global [%0], [%1], 16;" :: "r"(d), "l"(gsrc));
}
__device__ __forceinline__ void cp_commit() { asm volatile("cp.async.commit_group;"); }
template <int N>
__device__ __forceinline__ void cp_wait() {
    asm volatile("cp.async.wait_group %0;" :: "n"(N));
}

__device__ __forceinline__ unsigned pack2(float a, float b) {
    __half2 h = __floats2half2_rn(a, b);
    return *(unsigned*)&h;
}

// ---------------------------------------------------------------------------
// Prepass A: x -> fp16.
// ---------------------------------------------------------------------------
__global__ __launch_bounds__(256) void prepass_x(const float* __restrict__ x) {
    int i = blockIdx.x * 256 + threadIdx.x;
    float4 v = ((const float4*)x)[i];
    uint2 o;
    o.x = pack2(v.x, v.y);
    o.y = pack2(v.z, v.w);
    ((uint2*)g_Xr)[i] = o;
}

// ---------------------------------------------------------------------------
// Prepass B: transpose + fp16: g_Wr[w][n][k] = W[k][n].
// ---------------------------------------------------------------------------
__global__ __launch_bounds__(256) void prepass_w(const float* __restrict__ wq,
                                                 const float* __restrict__ wk,
                                                 const float* __restrict__ wv,
                                                 const float* __restrict__ wo) {
    __shared__ float t[32][33];
    const int w = blockIdx.z;
    const float* W = (w == 0) ? wq : (w == 1) ? wk : (w == 2) ? wv : wo;
    __half* D = g_Wr[w];
    const int k0 = blockIdx.y * 32, n0 = blockIdx.x * 32;
    const int tx = threadIdx.x & 31, ty = threadIdx.x >> 5;
#pragma unroll
    for (int j = 0; j < 4; j++)
        t[ty + 8 * j][tx] = W[(k0 + ty + 8 * j) * DM + n0 + tx];
    __syncthreads();
#pragma unroll
    for (int j = 0; j < 4; j++)
        D[(n0 + ty + 8 * j) * DM + k0 + tx] = __float2half_rn(t[tx][ty + 8 * j]);
}

// ---------------------------------------------------------------------------
// fp16 tensor-core GEMM: C[4096,1024] = A @ Wr^T (Wr is [n][k] fp16).
// Tile 128x128, BK=32, cp.async double-buffered, SINGLE barrier/iter.
// Fragments via ldmatrix.x4 (A: 4, B: 2 per kt). Static smem ~40 KB.
// ---------------------------------------------------------------------------
#define GSTR 40   // halves per row (32+8): 80B stride = 5x16B (cp.async-OK)

template <int MODE>
__global__ __launch_bounds__(256) void gemm_h(float* __restrict__ Cp) {
    __shared__ __align__(16) __half As[2][128 * GSTR];
    __shared__ __align__(16) __half Bs[2][128 * GSTR];

    const int tid = threadIdx.x;
    const int lane = tid & 31, wid = tid >> 5;
    const int g = lane >> 2, t = lane & 3;
    const int wm = wid & 1, wn = wid >> 1;
    const int row0 = blockIdx.y * 128;
    const int col0 = blockIdx.x * 128;
    const int z = (MODE == 0) ? 3 : blockIdx.z;

    const __half* A = (MODE == 0) ? (const __half*)g_O : (const __half*)g_Xr;
    const __half* B = g_Wr[z];

    // ldmatrix lane roles
    const int lr = lane & 7, quad = lane >> 3;
    const int arow = lr + (quad & 1) * 8;
    const int acol = (quad >> 1) * 8;
    const int brow = lr + (quad >> 1) * 8;
    const int bcol = (quad & 1) * 8;

    unsigned asb[2], bsb[2];
#pragma unroll
    for (int b = 0; b < 2; b++) {
        asb[b] = (unsigned)__cvta_generic_to_shared(&As[b][0]);
        bsb[b] = (unsigned)__cvta_generic_to_shared(&Bs[b][0]);
    }

    float acc[4][4][4] = {};

#define LOADT(k0, buf)                                                        \
    do {                                                                      \
        _Pragma("unroll")                                                     \
        for (int j = 0; j < 2; j++) {                                         \
            const int s = tid + j * 256;                                      \
            const int r = s >> 2, c = (s & 3) * 8;                            \
            cp16(&As[buf][r * GSTR + c], &A[(row0 + r) * DM + (k0) + c]);     \
            cp16(&Bs[buf][r * GSTR + c], &B[(col0 + r) * DM + (k0) + c]);     \
        }                                                                     \
        cp_commit();                                                          \
    } while (0)

    LOADT(0, 0);

    for (int it = 0; it < DM / 32; it++) {
        const int buf = it & 1;
        cp_wait<0>();        // own copies of tile `it` done
        __syncthreads();     // all copies visible; prior-iter reads done
        if (it + 1 < DM / 32) LOADT((it + 1) * 32, buf ^ 1);

#pragma unroll
        for (int kt = 0; kt < 2; kt++) {
            const int kk = kt * 16;
            unsigned a[4][4], b[4][2];
#pragma unroll
            for (int mi = 0; mi < 4; mi++)
                ldm_x4(a[mi][0], a[mi][1], a[mi][2], a[mi][3],
                       asb[buf] + ((wm * 64 + mi * 16 + arow) * GSTR + kk + acol) * 2);
#pragma unroll
            for (int pr = 0; pr < 2; pr++)
                ldm_x4(b[2 * pr][0], b[2 * pr][1], b[2 * pr + 1][0], b[2 * pr + 1][1],
                       bsb[buf] + ((wn * 32 + pr * 16 + brow) * GSTR + kk + bcol) * 2);
#pragma unroll
            for (int mi = 0; mi < 4; mi++)
#pragma unroll
                for (int ni = 0; ni < 4; ni++)
                    mma_f16(acc[mi][ni][0], acc[mi][ni][1], acc[mi][ni][2], acc[mi][ni][3],
                            a[mi][0], a[mi][1], a[mi][2], a[mi][3],
                            b[ni][0], b[ni][1]);
        }
    }
#undef LOADT

    if (MODE == 0) {
#pragma unroll
        for (int mi = 0; mi < 4; mi++) {
            const int r0 = row0 + wm * 64 + mi * 16 + g;
#pragma unroll
            for (int ni = 0; ni < 4; ni++) {
                const int c = col0 + wn * 32 + ni * 8 + 2 * t;
                *(float2*)&Cp[r0 * DM + c] = make_float2(acc[mi][ni][0], acc[mi][ni][1]);
                *(float2*)&Cp[(r0 + 8) * DM + c] = make_float2(acc[mi][ni][2], acc[mi][ni][3]);
            }
        }
    } else {
        __half* C = (z == 0) ? g_Q : (z == 1) ? g_K : g_V;
        // Q: fold 1/sqrt(64) and log2(e) so softmax runs in exp2 domain.
        const float sc = (z == 0) ? 0.125f * 1.4426950408889634f : 1.0f;
#pragma unroll
        for (int mi = 0; mi < 4; mi++) {
            const int r0 = row0 + wm * 64 + mi * 16 + g;
#pragma unroll
            for (int ni = 0; ni < 4; ni++) {
                const int c = col0 + wn * 32 + ni * 8 + 2 * t;
                const int hh = c >> 6, d = c & 63;
                __half* dst = &C[hh * (S_LEN * HD) + r0 * HD + d];
                *(unsigned*)dst = pack2(acc[mi][ni][0] * sc, acc[mi][ni][1] * sc);
                *(unsigned*)(dst + 8 * HD) = pack2(acc[mi][ni][2] * sc, acc[mi][ni][3] * sc);
            }
        }
    }
}

// ---------------------------------------------------------------------------
// Flash attention, fp16 mma, causal. Br=128, Bc=64, 8 warps (16-row stripes).
// Single barrier per KV iteration. K fragments via scalar LDS (measured
// faster than ldmatrix here — R12 regression); V via ldmatrix.trans.
// Softmax exp2-domain ex2.approx.f16x2; row sums via ones-MMA. Rescale
// skipped when the warp's running max is unchanged (exact: skips *1.0).
// Static smem ~36.9 KB.
// ---------------------------------------------------------------------------
#define KVS 72   // halves per row: 144B stride = 9x16B (cp.async-OK)

__global__ __launch_bounds__(256) void attn_h() {
    __shared__ __align__(16) __half Ks[2][64 * KVS];
    __shared__ __align__(16) __half Vs[2][64 * KVS];

    const int qb = (int)gridDim.x - 1 - (int)blockIdx.x;  // long CTAs first
    const int h  = blockIdx.y;
    const int tid = threadIdx.x;
    const int lane = tid & 31, wid = tid >> 5;
    const int g = lane >> 2, t = lane & 3;
    const int wm = wid;                   // 0..7 -> 16-row stripe

    const __half* Qh = g_Q + h * (S_LEN * HD);
    const __half* Kh = g_K + h * (S_LEN * HD);
    const __half* Vh = g_V + h * (S_LEN * HD);

    const int kb_end = 2 * qb + 1;        // inclusive; 64-col kv blocks

#define LOAD_KV(kb, buf)                                                      \
    do {                                                                      \
        _Pragma("unroll")                                                     \
        for (int j = 0; j < 2; j++) {                                         \
            const int s = tid + j * 256;                                      \
            const int r = s >> 3, c = (s & 7) * 8;                            \
            cp16(&Ks[buf][r * KVS + c], &Kh[((kb) * 64 + r) * HD + c]);       \
            cp16(&Vs[buf][r * KVS + c], &Vh[((kb) * 64 + r) * HD + c]);       \
        }                                                                     \
        cp_commit();                                                          \
    } while (0)

    LOAD_KV(0, 0);

    // Q fragments in registers (4 k16 blocks), rows qb*128 + wm*16 + {g, g+8}.
    unsigned qf[4][4];
    {
        const int q0 = qb * 128 + wm * 16 + g;
#pragma unroll
        for (int kt = 0; kt < 4; kt++) {
            const int kk = kt * 16;
            qf[kt][0] = *(const unsigned*)&Qh[q0 * HD + kk + 2 * t];
            qf[kt][1] = *(const unsigned*)&Qh[(q0 + 8) * HD + kk + 2 * t];
            qf[kt][2] = *(const unsigned*)&Qh[q0 * HD + kk + 2 * t + 8];
            qf[kt][3] = *(const unsigned*)&Qh[(q0 + 8) * HD + kk + 2 * t + 8];
        }
    }

    // ldmatrix.trans lane offsets for V
    const int lr = lane & 7, quad = lane >> 3;
    const int vrow = lr + (quad & 1) * 8;
    const int vcol = (quad >> 1) * 8;

    unsigned vsb[2];
#pragma unroll
    for (int b = 0; b < 2; b++)
        vsb[b] = (unsigned)__cvta_generic_to_shared(&Vs[b][0]);

    float m0 = NEG_INF, m1 = NEG_INF;
    float lac[4] = {};                    // row-sum accumulators (ones-MMA)
    float o[8][4] = {};

    for (int kb = 0; kb <= kb_end; kb++) {
        const int buf = kb & 1;
        cp_wait<0>();       // own copies of tile kb done
        __syncthreads();    // all copies visible; prior-iter reads done
        if (kb < kb_end) LOAD_KV(kb + 1, buf ^ 1);

        // ---- S = Q K^T : 16 rows x 64 cols per warp (scalar-LDS K frags) ----
        float s[8][4] = {};
#pragma unroll
        for (int kt = 0; kt < 4; kt++) {
            const int kk = kt * 16;
#pragma unroll
            for (int ni = 0; ni < 8; ni++) {
                const __half* bb = &Ks[buf][(ni * 8 + g) * KVS + kk];
                mma_f16(s[ni][0], s[ni][1], s[ni][2], s[ni][3],
                        qf[kt][0], qf[kt][1], qf[kt][2], qf[kt][3],
                        *(const unsigned*)&bb[2 * t],
                        *(const unsigned*)&bb[2 * t + 8]);
            }
        }

        // ---- causal mask (diagonal 64-blocks) ----
        if (kb >= 2 * qb) {
            const int rg0 = qb * 128 + wm * 16 + g;
            const int rg1 = rg0 + 8;
#pragma unroll
            for (int ni = 0; ni < 8; ni++) {
                const int cb = kb * 64 + ni * 8 + 2 * t;
                if (cb > rg0) s[ni][0] = NEG_INF;
                if (cb + 1 > rg0) s[ni][1] = NEG_INF;
                if (cb > rg1) s[ni][2] = NEG_INF;
                if (cb + 1 > rg1) s[ni][3] = NEG_INF;
            }
        }

        // ---- online max: tree reduction then 4-lane shuffles ----
        float a0[4], a1[4];
#pragma unroll
        for (int j = 0; j < 4; j++) {
            a0[j] = fmaxf(fmaxf(s[2 * j][0], s[2 * j][1]),
                          fmaxf(s[2 * j + 1][0], s[2 * j + 1][1]));
            a1[j] = fmaxf(fmaxf(s[2 * j][2], s[2 * j][3]),
                          fmaxf(s[2 * j + 1][2], s[2 * j + 1][3]));
        }
        float pm0 = fmaxf(fmaxf(a0[0], a0[1]), fmaxf(a0[2], a0[3]));
        float pm1 = fmaxf(fmaxf(a1[0], a1[1]), fmaxf(a1[2], a1[3]));
#pragma unroll
        for (int off = 1; off < 4; off <<= 1) {
            pm0 = fmaxf(pm0, __shfl_xor_sync(0xffffffffu, pm0, off, 4));
            pm1 = fmaxf(pm1, __shfl_xor_sync(0xffffffffu, pm1, off, 4));
        }
        const float mx0 = fmaxf(m0, pm0);
        const float mx1 = fmaxf(m1, pm1);
        const bool upd = (mx0 > m0) || (mx1 > m1);

        // ---- P = 2^(S-m) in fp16x2; packed regs ARE the PV A-fragments ----
        unsigned pp[8][2];
#pragma unroll
        for (int ni = 0; ni < 8; ni++) {
            unsigned e0 = pack2(s[ni][0] - mx0, s[ni][1] - mx0);
            unsigned e1 = pack2(s[ni][2] - mx1, s[ni][3] - mx1);
            asm("ex2.approx.f16x2 %0, %0;" : "+r"(e0));
            asm("ex2.approx.f16x2 %0, %0;" : "+r"(e1));
            pp[ni][0] = e0;
            pp[ni][1] = e1;
        }

        // ---- rescale accumulators (skipped when max unchanged warp-wide) ----
        if (__any_sync(0xffffffffu, upd)) {
            const float scl0 = exp2f(m0 - mx0);
            const float scl1 = exp2f(m1 - mx1);
            lac[0] *= scl0; lac[1] *= scl0; lac[2] *= scl1; lac[3] *= scl1;
#pragma unroll
            for (int ni = 0; ni < 8; ni++) {
                o[ni][0] *= scl0; o[ni][1] *= scl0;
                o[ni][2] *= scl1; o[ni][3] *= scl1;
            }
        }
        m0 = mx0; m1 = mx1;

        // ---- l += P @ 1 (ones-MMA, fp32 accum, consistent with PV's P) ----
#pragma unroll
        for (int jp = 0; jp < 4; jp++)
            mma_f16(lac[0], lac[1], lac[2], lac[3],
                    pp[2 * jp][0], pp[2 * jp][1],
                    pp[2 * jp + 1][0], pp[2 * jp + 1][1],
                    ONES2, ONES2);

        // ---- O += P V (ldmatrix.trans) ----
#pragma unroll
        for (int jp = 0; jp < 4; jp++) {
            const unsigned pa0 = pp[2 * jp][0], pa1 = pp[2 * jp][1];
            const unsigned pa2 = pp[2 * jp + 1][0], pa3 = pp[2 * jp + 1][1];
#pragma unroll
            for (int np = 0; np < 4; np++) {
                unsigned v0, v1, v2, v3;
                unsigned addr = vsb[buf] + ((jp * 16 + vrow) * KVS + np * 16 + vcol) * 2;
                asm volatile(
                    "ldmatrix.sync.aligned.m8n8.x4.trans.shared.b16 "
                    "{%0,%1,%2,%3}, [%4];"
                    : "=r"(v0), "=r"(v1), "=r"(v2), "=r"(v3) : "r"(addr));
                mma_f16(o[np * 2][0], o[np * 2][1], o[np * 2][2], o[np * 2][3],
                        pa0, pa1, pa2, pa3, v0, v1);
                mma_f16(o[np * 2 + 1][0], o[np * 2 + 1][1],
                        o[np * 2 + 1][2], o[np * 2 + 1][3],
                        pa0, pa1, pa2, pa3, v2, v3);
            }
        }
    }
#undef LOAD_KV

    {
        const float inv0 = 1.0f / lac[0];
        const float inv1 = 1.0f / lac[2];
        const int q0 = qb * 128 + wm * 16 + g;
#pragma unroll
        for (int ni = 0; ni < 8; ni++) {
            const int c = h * HD + ni * 8 + 2 * t;
            *(unsigned*)&g_O[q0 * DM + c] = pack2(o[ni][0] * inv0, o[ni][1] * inv0);
            *(unsigned*)&g_O[(q0 + 8) * DM + c] = pack2(o[ni][2] * inv1, o[ni][3] * inv1);
        }
    }
}

// ---------------------------------------------------------------------------
extern "C" void kernel_launch(void* const* d_in, const int* in_sizes, int n_in,
                              void* d_out, int out_size) {
    (void)in_sizes; (void)n_in; (void)out_size;
    const float* x  = (const float*)d_in[0];
    const float* Wq = (const float*)d_in[1];
    const float* Wk = (const float*)d_in[2];
    const float* Wv = (const float*)d_in[3];
    const float* Wo = (const float*)d_in[4];
    float* out = (float*)d_out;

    prepass_x<<<S_LEN * DM / 4 / 256, 256>>>(x);
    prepass_w<<<dim3(DM / 32, DM / 32, 4), 256>>>(Wq, Wk, Wv, Wo);

    gemm_h<1><<<dim3(DM / 128, S_LEN / 128, 3), 256>>>(nullptr);

    attn_h<<<dim3(S_LEN / 128, NH), 256>>>();

    gemm_h<0><<<dim3(DM / 128, S_LEN / 128, 1), 256>>>(out);
}

// round 14
// speedup vs baseline: 1.0290x; 1.0290x over previous
#include <cuda_runtime.h>
#include <cuda_fp16.h>
#include <cstdint>

#define S_LEN 4096
#define DM 1024
#define NH 16
#define HD 64
#define NEG_INF __int_as_float(0xff800000)
#define ONES2 0x3C003C00u   // half2 {1.0, 1.0}

// Scratch (device globals: allocation-free per harness rules). All fp16.
__device__ __half g_Q[NH * S_LEN * HD];  // [h][s][d], pre-scaled 0.125*log2(e)
__device__ __half g_K[NH * S_LEN * HD];
__device__ __half g_V[NH * S_LEN * HD];
__device__ __half g_O[S_LEN * DM];       // [s][h*64+d]
__device__ __half g_Xr[S_LEN * DM];      // x in fp16
__device__ __half g_Wr[4][DM * DM];      // W^T: [n][k], k contiguous

__device__ __forceinline__ void mma_f16(float& d0, float& d1, float& d2, float& d3,
                                        unsigned a0, unsigned a1, unsigned a2, unsigned a3,
                                        unsigned b0, unsigned b1) {
    asm volatile(
        "mma.sync.aligned.m16n8k16.row.col.f32.f16.f16.f32 "
        "{%0,%1,%2,%3}, {%4,%5,%6,%7}, {%8,%9}, {%0,%1,%2,%3};"
        : "+f"(d0), "+f"(d1), "+f"(d2), "+f"(d3)
        : "r"(a0), "r"(a1), "r"(a2), "r"(a3), "r"(b0), "r"(b1));
}

__device__ __forceinline__ void ldm_x4(unsigned& r0, unsigned& r1, unsigned& r2,
                                       unsigned& r3, unsigned addr) {
    asm volatile("ldmatrix.sync.aligned.m8n8.x4.shared.b16 {%0,%1,%2,%3}, [%4];"
                 : "=r"(r0), "=r"(r1), "=r"(r2), "=r"(r3) : "r"(addr));
}

__device__ __forceinline__ void cp16(void* smem_dst, const void* gsrc) {
    unsigned d = (unsigned)__cvta_generic_to_shared(smem_dst);
    asm volatile("cp.async.cg.shared.global [%0], [%1], 16;" :: "r"(d), "l"(gsrc));
}
__device__ __forceinline__ void cp_commit() { asm volatile("cp.async.commit_group;"); }
template <int N>
__device__ __forceinline__ void cp_wait() {
    asm volatile("cp.async.wait_group %0;" :: "n"(N));
}

__device__ __forceinline__ unsigned pack2(float a, float b) {
    __half2 h = __floats2half2_rn(a, b);
    return *(unsigned*)&h;
}

// ---------------------------------------------------------------------------
// Prepass A: x -> fp16.
// ---------------------------------------------------------------------------
__global__ __launch_bounds__(256) void prepass_x(const float* __restrict__ x) {
    int i = blockIdx.x * 256 + threadIdx.x;
    float4 v = ((const float4*)x)[i];
    uint2 o;
    o.x = pack2(v.x, v.y);
    o.y = pack2(v.z, v.w);
    ((uint2*)g_Xr)[i] = o;
}

// ---------------------------------------------------------------------------
// Prepass B: transpose + fp16: g_Wr[w][n][k] = W[k][n].
// ---------------------------------------------------------------------------
__global__ __launch_bounds__(256) void prepass_w(const float* __restrict__ wq,
                                                 const float* __restrict__ wk,
                                                 const float* __restrict__ wv,
                                                 const float* __restrict__ wo) {
    __shared__ float t[32][33];
    const int w = blockIdx.z;
    const float* W = (w == 0) ? wq : (w == 1) ? wk : (w == 2) ? wv : wo;
    __half* D = g_Wr[w];
    const int k0 = blockIdx.y * 32, n0 = blockIdx.x * 32;
    const int tx = threadIdx.x & 31, ty = threadIdx.x >> 5;
#pragma unroll
    for (int j = 0; j < 4; j++)
        t[ty + 8 * j][tx] = W[(k0 + ty + 8 * j) * DM + n0 + tx];
    __syncthreads();
#pragma unroll
    for (int j = 0; j < 4; j++)
        D[(n0 + ty + 8 * j) * DM + k0 + tx] = __float2half_rn(t[tx][ty + 8 * j]);
}

// ---------------------------------------------------------------------------
// fp16 tensor-core GEMM (R12 configuration — measured best).
// Tile 128x128, BK=32, cp.async double-buffered, SINGLE barrier/iter.
// Fragments via ldmatrix.x4 (A: 4, B: 2 per kt). Static smem ~40 KB.
// ---------------------------------------------------------------------------
#define GSTR 40   // halves per row (32+8): 80B stride = 5x16B (cp.async-OK)

template <int MODE>
__global__ __launch_bounds__(256) void gemm_h(float* __restrict__ Cp) {
    __shared__ __align__(16) __half As[2][128 * GSTR];
    __shared__ __align__(16) __half Bs[2][128 * GSTR];

    const int tid = threadIdx.x;
    const int lane = tid & 31, wid = tid >> 5;
    const int g = lane >> 2, t = lane & 3;
    const int wm = wid & 1, wn = wid >> 1;
    const int row0 = blockIdx.y * 128;
    const int col0 = blockIdx.x * 128;
    const int z = (MODE == 0) ? 3 : blockIdx.z;

    const __half* A = (MODE == 0) ? (const __half*)g_O : (const __half*)g_Xr;
    const __half* B = g_Wr[z];

    // ldmatrix lane roles
    const int lr = lane & 7, quad = lane >> 3;
    const int arow = lr + (quad & 1) * 8;
    const int acol = (quad >> 1) * 8;
    const int brow = lr + (quad >> 1) * 8;
    const int bcol = (quad & 1) * 8;

    unsigned asb[2], bsb[2];
#pragma unroll
    for (int b = 0; b < 2; b++) {
        asb[b] = (unsigned)__cvta_generic_to_shared(&As[b][0]);
        bsb[b] = (unsigned)__cvta_generic_to_shared(&Bs[b][0]);
    }

    float acc[4][4][4] = {};

#define LOADT(k0, buf)                                                        \
    do {                                                                      \
        _Pragma("unroll")                                                     \
        for (int j = 0; j < 2; j++) {                                         \
            const int s = tid + j * 256;                                      \
            const int r = s >> 2, c = (s & 3) * 8;                            \
            cp16(&As[buf][r * GSTR + c], &A[(row0 + r) * DM + (k0) + c]);     \
            cp16(&Bs[buf][r * GSTR + c], &B[(col0 + r) * DM + (k0) + c]);     \
        }                                                                     \
        cp_commit();                                                          \
    } while (0)

    LOADT(0, 0);

    for (int it = 0; it < DM / 32; it++) {
        const int buf = it & 1;
        cp_wait<0>();        // own copies of tile `it` done
        __syncthreads();     // all copies visible; prior-iter reads done
        if (it + 1 < DM / 32) LOADT((it + 1) * 32, buf ^ 1);

#pragma unroll
        for (int kt = 0; kt < 2; kt++) {
            const int kk = kt * 16;
            unsigned a[4][4], b[4][2];
#pragma unroll
            for (int mi = 0; mi < 4; mi++)
                ldm_x4(a[mi][0], a[mi][1], a[mi][2], a[mi][3],
                       asb[buf] + ((wm * 64 + mi * 16 + arow) * GSTR + kk + acol) * 2);
#pragma unroll
            for (int pr = 0; pr < 2; pr++)
                ldm_x4(b[2 * pr][0], b[2 * pr][1], b[2 * pr + 1][0], b[2 * pr + 1][1],
                       bsb[buf] + ((wn * 32 + pr * 16 + brow) * GSTR + kk + bcol) * 2);
#pragma unroll
            for (int mi = 0; mi < 4; mi++)
#pragma unroll
                for (int ni = 0; ni < 4; ni++)
                    mma_f16(acc[mi][ni][0], acc[mi][ni][1], acc[mi][ni][2], acc[mi][ni][3],
                            a[mi][0], a[mi][1], a[mi][2], a[mi][3],
                            b[ni][0], b[ni][1]);
        }
    }
#undef LOADT

    if (MODE == 0) {
#pragma unroll
        for (int mi = 0; mi < 4; mi++) {
            const int r0 = row0 + wm * 64 + mi * 16 + g;
#pragma unroll
            for (int ni = 0; ni < 4; ni++) {
                const int c = col0 + wn * 32 + ni * 8 + 2 * t;
                *(float2*)&Cp[r0 * DM + c] = make_float2(acc[mi][ni][0], acc[mi][ni][1]);
                *(float2*)&Cp[(r0 + 8) * DM + c] = make_float2(acc[mi][ni][2], acc[mi][ni][3]);
            }
        }
    } else {
        __half* C = (z == 0) ? g_Q : (z == 1) ? g_K : g_V;
        // Q: fold 1/sqrt(64) and log2(e) so softmax runs in exp2 domain.
        const float sc = (z == 0) ? 0.125f * 1.4426950408889634f : 1.0f;
#pragma unroll
        for (int mi = 0; mi < 4; mi++) {
            const int r0 = row0 + wm * 64 + mi * 16 + g;
#pragma unroll
            for (int ni = 0; ni < 4; ni++) {
                const int c = col0 + wn * 32 + ni * 8 + 2 * t;
                const int hh = c >> 6, d = c & 63;
                __half* dst = &C[hh * (S_LEN * HD) + r0 * HD + d];
                *(unsigned*)dst = pack2(acc[mi][ni][0] * sc, acc[mi][ni][1] * sc);
                *(unsigned*)(dst + 8 * HD) = pack2(acc[mi][ni][2] * sc, acc[mi][ni][3] * sc);
            }
        }
    }
}

// ---------------------------------------------------------------------------
// Flash attention (R11 configuration — measured best, 177.5 us).
// fp16 mma, causal. Br=128, Bc=64, 8 warps (16-row stripes). Single barrier
// per KV iteration. Scalar-LDS K fragments; V via ldmatrix.trans. Softmax
// exp2-domain ex2.approx.f16x2; row sums via ones-MMA; unconditional rescale.
// Static smem ~36.9 KB.
// ---------------------------------------------------------------------------
#define KVS 72   // halves per row: 144B stride = 9x16B (cp.async-OK)

__global__ __launch_bounds__(256) void attn_h() {
    __shared__ __align__(16) __half Ks[2][64 * KVS];
    __shared__ __align__(16) __half Vs[2][64 * KVS];

    const int qb = (int)gridDim.x - 1 - (int)blockIdx.x;  // long CTAs first
    const int h  = blockIdx.y;
    const int tid = threadIdx.x;
    const int lane = tid & 31, wid = tid >> 5;
    const int g = lane >> 2, t = lane & 3;
    const int wm = wid;                   // 0..7 -> 16-row stripe

    const __half* Qh = g_Q + h * (S_LEN * HD);
    const __half* Kh = g_K + h * (S_LEN * HD);
    const __half* Vh = g_V + h * (S_LEN * HD);

    const int kb_end = 2 * qb + 1;        // inclusive; 64-col kv blocks

#define LOAD_KV(kb, buf)                                                      \
    do {                                                                      \
        _Pragma("unroll")                                                     \
        for (int j = 0; j < 2; j++) {                                         \
            const int s = tid + j * 256;                                      \
            const int r = s >> 3, c = (s & 7) * 8;                            \
            cp16(&Ks[buf][r * KVS + c], &Kh[((kb) * 64 + r) * HD + c]);       \
            cp16(&Vs[buf][r * KVS + c], &Vh[((kb) * 64 + r) * HD + c]);       \
        }                                                                     \
        cp_commit();                                                          \
    } while (0)

    LOAD_KV(0, 0);

    // Q fragments in registers (4 k16 blocks), rows qb*128 + wm*16 + {g, g+8}.
    unsigned qf[4][4];
    {
        const int q0 = qb * 128 + wm * 16 + g;
#pragma unroll
        for (int kt = 0; kt < 4; kt++) {
            const int kk = kt * 16;
            qf[kt][0] = *(const unsigned*)&Qh[q0 * HD + kk + 2 * t];
            qf[kt][1] = *(const unsigned*)&Qh[(q0 + 8) * HD + kk + 2 * t];
            qf[kt][2] = *(const unsigned*)&Qh[q0 * HD + kk + 2 * t + 8];
            qf[kt][3] = *(const unsigned*)&Qh[(q0 + 8) * HD + kk + 2 * t + 8];
        }
    }

    // ldmatrix.trans lane offsets for V
    const int lr = lane & 7, quad = lane >> 3;
    const int vrow = lr + (quad & 1) * 8;
    const int vcol = (quad >> 1) * 8;

    unsigned vsb[2];
#pragma unroll
    for (int b = 0; b < 2; b++)
        vsb[b] = (unsigned)__cvta_generic_to_shared(&Vs[b][0]);

    float m0 = NEG_INF, m1 = NEG_INF;
    float lac[4] = {};                    // row-sum accumulators (ones-MMA)
    float o[8][4] = {};

    for (int kb = 0; kb <= kb_end; kb++) {
        const int buf = kb & 1;
        cp_wait<0>();       // own copies of tile kb done
        __syncthreads();    // all copies visible; prior-iter reads done
        if (kb < kb_end) LOAD_KV(kb + 1, buf ^ 1);

        // ---- S = Q K^T : 16 rows x 64 cols per warp (scalar-LDS K frags) ----
        float s[8][4] = {};
#pragma unroll
        for (int kt = 0; kt < 4; kt++) {
            const int kk = kt * 16;
#pragma unroll
            for (int ni = 0; ni < 8; ni++) {
                const __half* bb = &Ks[buf][(ni * 8 + g) * KVS + kk];
                mma_f16(s[ni][0], s[ni][1], s[ni][2], s[ni][3],
                        qf[kt][0], qf[kt][1], qf[kt][2], qf[kt][3],
                        *(const unsigned*)&bb[2 * t],
                        *(const unsigned*)&bb[2 * t + 8]);
            }
        }

        // ---- causal mask (diagonal 64-blocks) ----
        if (kb >= 2 * qb) {
            const int rg0 = qb * 128 + wm * 16 + g;
            const int rg1 = rg0 + 8;
#pragma unroll
            for (int ni = 0; ni < 8; ni++) {
                const int cb = kb * 64 + ni * 8 + 2 * t;
                if (cb > rg0) s[ni][0] = NEG_INF;
                if (cb + 1 > rg0) s[ni][1] = NEG_INF;
                if (cb > rg1) s[ni][2] = NEG_INF;
                if (cb + 1 > rg1) s[ni][3] = NEG_INF;
            }
        }

        // ---- online max (warp-local, exp2 domain) ----
        float pm0 = fmaxf(s[0][0], s[0][1]);
        float pm1 = fmaxf(s[0][2], s[0][3]);
#pragma unroll
        for (int ni = 1; ni < 8; ni++) {
            pm0 = fmaxf(pm0, fmaxf(s[ni][0], s[ni][1]));
            pm1 = fmaxf(pm1, fmaxf(s[ni][2], s[ni][3]));
        }
#pragma unroll
        for (int off = 1; off < 4; off <<= 1) {
            pm0 = fmaxf(pm0, __shfl_xor_sync(0xffffffffu, pm0, off, 4));
            pm1 = fmaxf(pm1, __shfl_xor_sync(0xffffffffu, pm1, off, 4));
        }
        const float mx0 = fmaxf(m0, pm0);
        const float mx1 = fmaxf(m1, pm1);
        const float scl0 = exp2f(m0 - mx0);
        const float scl1 = exp2f(m1 - mx1);
        m0 = mx0; m1 = mx1;

        // ---- P = 2^(S-m) in fp16x2; packed regs ARE the PV A-fragments ----
        unsigned pp[8][2];
#pragma unroll
        for (int ni = 0; ni < 8; ni++) {
            unsigned e0 = pack2(s[ni][0] - mx0, s[ni][1] - mx0);
            unsigned e1 = pack2(s[ni][2] - mx1, s[ni][3] - mx1);
            asm("ex2.approx.f16x2 %0, %0;" : "+r"(e0));
            asm("ex2.approx.f16x2 %0, %0;" : "+r"(e1));
            pp[ni][0] = e0;
            pp[ni][1] = e1;
        }

        // ---- rescale accumulators ----
        lac[0] *= scl0; lac[1] *= scl0; lac[2] *= scl1; lac[3] *= scl1;
#pragma unroll
        for (int ni = 0; ni < 8; ni++) {
            o[ni][0] *= scl0; o[ni][1] *= scl0;
            o[ni][2] *= scl1; o[ni][3] *= scl1;
        }

        // ---- l += P @ 1 (ones-MMA, fp32 accum, consistent with PV's P) ----
#pragma unroll
        for (int jp = 0; jp < 4; jp++)
            mma_f16(lac[0], lac[1], lac[2], lac[3],
                    pp[2 * jp][0], pp[2 * jp][1],
                    pp[2 * jp + 1][0], pp[2 * jp + 1][1],
                    ONES2, ONES2);

        // ---- O += P V (ldmatrix.trans) ----
#pragma unroll
        for (int jp = 0; jp < 4; jp++) {
            const unsigned pa0 = pp[2 * jp][0], pa1 = pp[2 * jp][1];
            const unsigned pa2 = pp[2 * jp + 1][0], pa3 = pp[2 * jp + 1][1];
#pragma unroll
            for (int np = 0; np < 4; np++) {
                unsigned v0, v1, v2, v3;
                unsigned addr = vsb[buf] + ((jp * 16 + vrow) * KVS + np * 16 + vcol) * 2;
                asm volatile(
                    "ldmatrix.sync.aligned.m8n8.x4.trans.shared.b16 "
                    "{%0,%1,%2,%3}, [%4];"
                    : "=r"(v0), "=r"(v1), "=r"(v2), "=r"(v3) : "r"(addr));
                mma_f16(o[np * 2][0], o[np * 2][1], o[np * 2][2], o[np * 2][3],
                        pa0, pa1, pa2, pa3, v0, v1);
                mma_f16(o[np * 2 + 1][0], o[np * 2 + 1][1],
                        o[np * 2 + 1][2], o[np * 2 + 1][3],
                        pa0, pa1, pa2, pa3, v2, v3);
            }
        }
    }
#undef LOAD_KV

    {
        const float inv0 = 1.0f / lac[0];
        const float inv1 = 1.0f / lac[2];
        const int q0 = qb * 128 + wm * 16 + g;
#pragma unroll
        for (int ni = 0; ni < 8; ni++) {
            const int c = h * HD + ni * 8 + 2 * t;
            *(unsigned*)&g_O[q0 * DM + c] = pack2(o[ni][0] * inv0, o[ni][1] * inv0);
            *(unsigned*)&g_O[(q0 + 8) * DM + c] = pack2(o[ni][2] * inv1, o[ni][3] * inv1);
        }
    }
}

// ---------------------------------------------------------------------------
extern "C" void kernel_launch(void* const* d_in, const int* in_sizes, int n_in,
                              void* d_out, int out_size) {
    (void)in_sizes; (void)n_in; (void)out_size;
    const float* x  = (const float*)d_in[0];
    const float* Wq = (const float*)d_in[1];
    const float* Wk = (const float*)d_in[2];
    const float* Wv = (const float*)d_in[3];
    const float* Wo = (const float*)d_in[4];
    float* out = (float*)d_out;

    prepass_x<<<S_LEN * DM / 4 / 256, 256>>>(x);
    prepass_w<<<dim3(DM / 32, DM / 32, 4), 256>>>(Wq, Wk, Wv, Wo);

    gemm_h<1><<<dim3(DM / 128, S_LEN / 128, 3), 256>>>(nullptr);

    attn_h<<<dim3(S_LEN / 128, NH), 256>>>();

    gemm_h<0><<<dim3(DM / 128, S_LEN / 128, 1), 256>>>(out);
}

// round 16
// speedup vs baseline: 1.1058x; 1.0746x over previous
#include <cuda_runtime.h>
#include <cuda_fp16.h>
#include <cstdint>

#define S_LEN 4096
#define DM 1024
#define NH 16
#define HD 64
#define NEG_INF __int_as_float(0xff800000)
#define ONES2 0x3C003C00u   // half2 {1.0, 1.0}

// Scratch (device globals: allocation-free per harness rules). All fp16.
__device__ __half g_Q[NH * S_LEN * HD];  // [h][s][d], pre-scaled 0.125*log2(e)
__device__ __half g_K[NH * S_LEN * HD];
__device__ __half g_V[NH * S_LEN * HD];
__device__ __half g_O[S_LEN * DM];       // [s][h*64+d]
__device__ __half g_Xr[S_LEN * DM];      // x in fp16
__device__ __half g_Wr[4][DM * DM];      // W^T: [n][k], k contiguous

__device__ __forceinline__ void mma_f16(float& d0, float& d1, float& d2, float& d3,
                                        unsigned a0, unsigned a1, unsigned a2, unsigned a3,
                                        unsigned b0, unsigned b1) {
    asm volatile(
        "mma.sync.aligned.m16n8k16.row.col.f32.f16.f16.f32 "
        "{%0,%1,%2,%3}, {%4,%5,%6,%7}, {%8,%9}, {%0,%1,%2,%3};"
        : "+f"(d0), "+f"(d1), "+f"(d2), "+f"(d3)
        : "r"(a0), "r"(a1), "r"(a2), "r"(a3), "r"(b0), "r"(b1));
}

__device__ __forceinline__ void ldm_x4(unsigned& r0, unsigned& r1, unsigned& r2,
                                       unsigned& r3, unsigned addr) {
    asm volatile("ldmatrix.sync.aligned.m8n8.x4.shared.b16 {%0,%1,%2,%3}, [%4];"
                 : "=r"(r0), "=r"(r1), "=r"(r2), "=r"(r3) : "r"(addr));
}

__device__ __forceinline__ void cp16(void* smem_dst, const void* gsrc) {
    unsigned d = (unsigned)__cvta_generic_to_shared(smem_dst);
    asm volatile("cp.async.cg.shared.global [%0], [%1], 16;" :: "r"(d), "l"(gsrc));
}
__device__ __forceinline__ void cp_commit() { asm volatile("cp.async.commit_group;"); }
template <int N>
__device__ __forceinline__ void cp_wait() {
    asm volatile("cp.async.wait_group %0;" :: "n"(N));
}

__device__ __forceinline__ unsigned pack2(float a, float b) {
    __half2 h = __floats2half2_rn(a, b);
    return *(unsigned*)&h;
}

// ---------------------------------------------------------------------------
// Prepass A: x -> fp16.
// ---------------------------------------------------------------------------
__global__ __launch_bounds__(256) void prepass_x(const float* __restrict__ x) {
    int i = blockIdx.x * 256 + threadIdx.x;
    float4 v = ((const float4*)x)[i];
    uint2 o;
    o.x = pack2(v.x, v.y);
    o.y = pack2(v.z, v.w);
    ((uint2*)g_Xr)[i] = o;
}

// ---------------------------------------------------------------------------
// Prepass B: transpose + fp16: g_Wr[w][n][k] = W[k][n].
// ---------------------------------------------------------------------------
__global__ __launch_bounds__(256) void prepass_w(const float* __restrict__ wq,
                                                 const float* __restrict__ wk,
                                                 const float* __restrict__ wv,
                                                 const float* __restrict__ wo) {
    __shared__ float t[32][33];
    const int w = blockIdx.z;
    const float* W = (w == 0) ? wq : (w == 1) ? wk : (w == 2) ? wv : wo;
    __half* D = g_Wr[w];
    const int k0 = blockIdx.y * 32, n0 = blockIdx.x * 32;
    const int tx = threadIdx.x & 31, ty = threadIdx.x >> 5;
#pragma unroll
    for (int j = 0; j < 4; j++)
        t[ty + 8 * j][tx] = W[(k0 + ty + 8 * j) * DM + n0 + tx];
    __syncthreads();
#pragma unroll
    for (int j = 0; j < 4; j++)
        D[(n0 + ty + 8 * j) * DM + k0 + tx] = __float2half_rn(t[tx][ty + 8 * j]);
}

// ---------------------------------------------------------------------------
// fp16 tensor-core GEMM (R12 configuration — measured best).
// Tile 128x128, BK=32, cp.async double-buffered, SINGLE barrier/iter.
// Fragments via ldmatrix.x4 (A: 4, B: 2 per kt). Static smem ~40 KB.
// ---------------------------------------------------------------------------
#define GSTR 40   // halves per row (32+8): 80B stride = 5x16B (cp.async-OK)

template <int MODE>
__global__ __launch_bounds__(256) void gemm_h(float* __restrict__ Cp) {
    __shared__ __align__(16) __half As[2][128 * GSTR];
    __shared__ __align__(16) __half Bs[2][128 * GSTR];

    const int tid = threadIdx.x;
    const int lane = tid & 31, wid = tid >> 5;
    const int g = lane >> 2, t = lane & 3;
    const int wm = wid & 1, wn = wid >> 1;
    const int row0 = blockIdx.y * 128;
    const int col0 = blockIdx.x * 128;
    const int z = (MODE == 0) ? 3 : blockIdx.z;

    const __half* A = (MODE == 0) ? (const __half*)g_O : (const __half*)g_Xr;
    const __half* B = g_Wr[z];

    // ldmatrix lane roles
    const int lr = lane & 7, quad = lane >> 3;
    const int arow = lr + (quad & 1) * 8;
    const int acol = (quad >> 1) * 8;
    const int brow = lr + (quad >> 1) * 8;
    const int bcol = (quad & 1) * 8;

    unsigned asb[2], bsb[2];
#pragma unroll
    for (int b = 0; b < 2; b++) {
        asb[b] = (unsigned)__cvta_generic_to_shared(&As[b][0]);
        bsb[b] = (unsigned)__cvta_generic_to_shared(&Bs[b][0]);
    }

    float acc[4][4][4] = {};

#define LOADT(k0, buf)                                                        \
    do {                                                                      \
        _Pragma("unroll")                                                     \
        for (int j = 0; j < 2; j++) {                                         \
            const int s = tid + j * 256;                                      \
            const int r = s >> 2, c = (s & 3) * 8;                            \
            cp16(&As[buf][r * GSTR + c], &A[(row0 + r) * DM + (k0) + c]);     \
            cp16(&Bs[buf][r * GSTR + c], &B[(col0 + r) * DM + (k0) + c]);     \
        }                                                                     \
        cp_commit();                                                          \
    } while (0)

    LOADT(0, 0);

    for (int it = 0; it < DM / 32; it++) {
        const int buf = it & 1;
        cp_wait<0>();        // own copies of tile `it` done
        __syncthreads();     // all copies visible; prior-iter reads done
        if (it + 1 < DM / 32) LOADT((it + 1) * 32, buf ^ 1);

#pragma unroll
        for (int kt = 0; kt < 2; kt++) {
            const int kk = kt * 16;
            unsigned a[4][4], b[4][2];
#pragma unroll
            for (int mi = 0; mi < 4; mi++)
                ldm_x4(a[mi][0], a[mi][1], a[mi][2], a[mi][3],
                       asb[buf] + ((wm * 64 + mi * 16 + arow) * GSTR + kk + acol) * 2);
#pragma unroll
            for (int pr = 0; pr < 2; pr++)
                ldm_x4(b[2 * pr][0], b[2 * pr][1], b[2 * pr + 1][0], b[2 * pr + 1][1],
                       bsb[buf] + ((wn * 32 + pr * 16 + brow) * GSTR + kk + bcol) * 2);
#pragma unroll
            for (int mi = 0; mi < 4; mi++)
#pragma unroll
                for (int ni = 0; ni < 4; ni++)
                    mma_f16(acc[mi][ni][0], acc[mi][ni][1], acc[mi][ni][2], acc[mi][ni][3],
                            a[mi][0], a[mi][1], a[mi][2], a[mi][3],
                            b[ni][0], b[ni][1]);
        }
    }
#undef LOADT

    if (MODE == 0) {
#pragma unroll
        for (int mi = 0; mi < 4; mi++) {
            const int r0 = row0 + wm * 64 + mi * 16 + g;
#pragma unroll
            for (int ni = 0; ni < 4; ni++) {
                const int c = col0 + wn * 32 + ni * 8 + 2 * t;
                *(float2*)&Cp[r0 * DM + c] = make_float2(acc[mi][ni][0], acc[mi][ni][1]);
                *(float2*)&Cp[(r0 + 8) * DM + c] = make_float2(acc[mi][ni][2], acc[mi][ni][3]);
            }
        }
    } else {
        __half* C = (z == 0) ? g_Q : (z == 1) ? g_K : g_V;
        // Q: fold 1/sqrt(64) and log2(e) so softmax runs in exp2 domain.
        const float sc = (z == 0) ? 0.125f * 1.4426950408889634f : 1.0f;
#pragma unroll
        for (int mi = 0; mi < 4; mi++) {
            const int r0 = row0 + wm * 64 + mi * 16 + g;
#pragma unroll
            for (int ni = 0; ni < 4; ni++) {
                const int c = col0 + wn * 32 + ni * 8 + 2 * t;
                const int hh = c >> 6, d = c & 63;
                __half* dst = &C[hh * (S_LEN * HD) + r0 * HD + d];
                *(unsigned*)dst = pack2(acc[mi][ni][0] * sc, acc[mi][ni][1] * sc);
                *(unsigned*)(dst + 8 * HD) = pack2(acc[mi][ni][2] * sc, acc[mi][ni][3] * sc);
            }
        }
    }
}

// ---------------------------------------------------------------------------
// Flash attention, fp16 mma, causal. Br=64, Bc=64, 4 warps (16-row stripes),
// 128 threads/CTA -> ~16K regs/CTA -> 4 CTAs/SM (vs 2): independent CTAs
// interleave softmax and mma phases. Per-warp code identical to R11.
// Single barrier per KV iteration; scalar-LDS K frags; V ldmatrix.trans;
// exp2-domain ex2.approx.f16x2; ones-MMA row sums. Static smem ~36.9 KB.
// ---------------------------------------------------------------------------
#define KVS 72   // halves per row: 144B stride = 9x16B (cp.async-OK)

__global__ __launch_bounds__(128) void attn_h() {
    __shared__ __align__(16) __half Ks[2][64 * KVS];
    __shared__ __align__(16) __half Vs[2][64 * KVS];

    const int qb = (int)gridDim.x - 1 - (int)blockIdx.x;  // long CTAs first
    const int h  = blockIdx.y;
    const int tid = threadIdx.x;
    const int lane = tid & 31, wid = tid >> 5;
    const int g = lane >> 2, t = lane & 3;
    const int wm = wid;                   // 0..3 -> 16-row stripe

    const __half* Qh = g_Q + h * (S_LEN * HD);
    const __half* Kh = g_K + h * (S_LEN * HD);
    const __half* Vh = g_V + h * (S_LEN * HD);

    const int kb_end = qb;                // inclusive; 64-col kv blocks

    // 64 rows x 64 halves = 512 16B-segs per matrix; 4 K + 4 V per thread.
#define LOAD_KV(kb, buf)                                                      \
    do {                                                                      \
        _Pragma("unroll")                                                     \
        for (int j = 0; j < 4; j++) {                                         \
            const int s = tid + j * 128;                                      \
            const int r = s >> 3, c = (s & 7) * 8;                            \
            cp16(&Ks[buf][r * KVS + c], &Kh[((kb) * 64 + r) * HD + c]);       \
            cp16(&Vs[buf][r * KVS + c], &Vh[((kb) * 64 + r) * HD + c]);       \
        }                                                                     \
        cp_commit();                                                          \
    } while (0)

    LOAD_KV(0, 0);

    // Q fragments in registers (4 k16 blocks), rows qb*64 + wm*16 + {g, g+8}.
    unsigned qf[4][4];
    {
        const int q0 = qb * 64 + wm * 16 + g;
#pragma unroll
        for (int kt = 0; kt < 4; kt++) {
            const int kk = kt * 16;
            qf[kt][0] = *(const unsigned*)&Qh[q0 * HD + kk + 2 * t];
            qf[kt][1] = *(const unsigned*)&Qh[(q0 + 8) * HD + kk + 2 * t];
            qf[kt][2] = *(const unsigned*)&Qh[q0 * HD + kk + 2 * t + 8];
            qf[kt][3] = *(const unsigned*)&Qh[(q0 + 8) * HD + kk + 2 * t + 8];
        }
    }

    // ldmatrix.trans lane offsets for V
    const int lr = lane & 7, quad = lane >> 3;
    const int vrow = lr + (quad & 1) * 8;
    const int vcol = (quad >> 1) * 8;

    unsigned vsb[2];
#pragma unroll
    for (int b = 0; b < 2; b++)
        vsb[b] = (unsigned)__cvta_generic_to_shared(&Vs[b][0]);

    float m0 = NEG_INF, m1 = NEG_INF;
    float lac[4] = {};                    // row-sum accumulators (ones-MMA)
    float o[8][4] = {};

    for (int kb = 0; kb <= kb_end; kb++) {
        const int buf = kb & 1;
        cp_wait<0>();       // own copies of tile kb done
        __syncthreads();    // all copies visible; prior-iter reads done
        if (kb < kb_end) LOAD_KV(kb + 1, buf ^ 1);

        // ---- S = Q K^T : 16 rows x 64 cols per warp (scalar-LDS K frags) ----
        float s[8][4] = {};
#pragma unroll
        for (int kt = 0; kt < 4; kt++) {
            const int kk = kt * 16;
#pragma unroll
            for (int ni = 0; ni < 8; ni++) {
                const __half* bb = &Ks[buf][(ni * 8 + g) * KVS + kk];
                mma_f16(s[ni][0], s[ni][1], s[ni][2], s[ni][3],
                        qf[kt][0], qf[kt][1], qf[kt][2], qf[kt][3],
                        *(const unsigned*)&bb[2 * t],
                        *(const unsigned*)&bb[2 * t + 8]);
            }
        }

        // ---- causal mask (diagonal block kb == qb only) ----
        if (kb >= qb) {
            const int rg0 = qb * 64 + wm * 16 + g;
            const int rg1 = rg0 + 8;
#pragma unroll
            for (int ni = 0; ni < 8; ni++) {
                const int cb = kb * 64 + ni * 8 + 2 * t;
                if (cb > rg0) s[ni][0] = NEG_INF;
                if (cb + 1 > rg0) s[ni][1] = NEG_INF;
                if (cb > rg1) s[ni][2] = NEG_INF;
                if (cb + 1 > rg1) s[ni][3] = NEG_INF;
            }
        }

        // ---- online max (warp-local, exp2 domain) ----
        float pm0 = fmaxf(s[0][0], s[0][1]);
        float pm1 = fmaxf(s[0][2], s[0][3]);
#pragma unroll
        for (int ni = 1; ni < 8; ni++) {
            pm0 = fmaxf(pm0, fmaxf(s[ni][0], s[ni][1]));
            pm1 = fmaxf(pm1, fmaxf(s[ni][2], s[ni][3]));
        }
#pragma unroll
        for (int off = 1; off < 4; off <<= 1) {
            pm0 = fmaxf(pm0, __shfl_xor_sync(0xffffffffu, pm0, off, 4));
            pm1 = fmaxf(pm1, __shfl_xor_sync(0xffffffffu, pm1, off, 4));
        }
        const float mx0 = fmaxf(m0, pm0);
        const float mx1 = fmaxf(m1, pm1);
        const float scl0 = exp2f(m0 - mx0);
        const float scl1 = exp2f(m1 - mx1);
        m0 = mx0; m1 = mx1;

        // ---- P = 2^(S-m) in fp16x2; packed regs ARE the PV A-fragments ----
        unsigned pp[8][2];
#pragma unroll
        for (int ni = 0; ni < 8; ni++) {
            unsigned e0 = pack2(s[ni][0] - mx0, s[ni][1] - mx0);
            unsigned e1 = pack2(s[ni][2] - mx1, s[ni][3] - mx1);
            asm("ex2.approx.f16x2 %0, %0;" : "+r"(e0));
            asm("ex2.approx.f16x2 %0, %0;" : "+r"(e1));
            pp[ni][0] = e0;
            pp[ni][1] = e1;
        }

        // ---- rescale accumulators ----
        lac[0] *= scl0; lac[1] *= scl0; lac[2] *= scl1; lac[3] *= scl1;
#pragma unroll
        for (int ni = 0; ni < 8; ni++) {
            o[ni][0] *= scl0; o[ni][1] *= scl0;
            o[ni][2] *= scl1; o[ni][3] *= scl1;
        }

        // ---- l += P @ 1 (ones-MMA, fp32 accum, consistent with PV's P) ----
#pragma unroll
        for (int jp = 0; jp < 4; jp++)
            mma_f16(lac[0], lac[1], lac[2], lac[3],
                    pp[2 * jp][0], pp[2 * jp][1],
                    pp[2 * jp + 1][0], pp[2 * jp + 1][1],
                    ONES2, ONES2);

        // ---- O += P V (ldmatrix.trans) ----
#pragma unroll
        for (int jp = 0; jp < 4; jp++) {
            const unsigned pa0 = pp[2 * jp][0], pa1 = pp[2 * jp][1];
            const unsigned pa2 = pp[2 * jp + 1][0], pa3 = pp[2 * jp + 1][1];
#pragma unroll
            for (int np = 0; np < 4; np++) {
                unsigned v0, v1, v2, v3;
                unsigned addr = vsb[buf] + ((jp * 16 + vrow) * KVS + np * 16 + vcol) * 2;
                asm volatile(
                    "ldmatrix.sync.aligned.m8n8.x4.trans.shared.b16 "
                    "{%0,%1,%2,%3}, [%4];"
                    : "=r"(v0), "=r"(v1), "=r"(v2), "=r"(v3) : "r"(addr));
                mma_f16(o[np * 2][0], o[np * 2][1], o[np * 2][2], o[np * 2][3],
                        pa0, pa1, pa2, pa3, v0, v1);
                mma_f16(o[np * 2 + 1][0], o[np * 2 + 1][1],
                        o[np * 2 + 1][2], o[np * 2 + 1][3],
                        pa0, pa1, pa2, pa3, v2, v3);
            }
        }
    }
#undef LOAD_KV

    {
        const float inv0 = 1.0f / lac[0];
        const float inv1 = 1.0f / lac[2];
        const int q0 = qb * 64 + wm * 16 + g;
#pragma unroll
        for (int ni = 0; ni < 8; ni++) {
            const int c = h * HD + ni * 8 + 2 * t;
            *(unsigned*)&g_O[q0 * DM + c] = pack2(o[ni][0] * inv0, o[ni][1] * inv0);
            *(unsigned*)&g_O[(q0 + 8) * DM + c] = pack2(o[ni][2] * inv1, o[ni][3] * inv1);
        }
    }
}

// ---------------------------------------------------------------------------
extern "C" void kernel_launch(void* const* d_in, const int* in_sizes, int n_in,
                              void* d_out, int out_size) {
    (void)in_sizes; (void)n_in; (void)out_size;
    const float* x  = (const float*)d_in[0];
    const float* Wq = (const float*)d_in[1];
    const float* Wk = (const float*)d_in[2];
    const float* Wv = (const float*)d_in[3];
    const float* Wo = (const float*)d_in[4];
    float* out = (float*)d_out;

    prepass_x<<<S_LEN * DM / 4 / 256, 256>>>(x);
    prepass_w<<<dim3(DM / 32, DM / 32, 4), 256>>>(Wq, Wk, Wv, Wo);

    gemm_h<1><<<dim3(DM / 128, S_LEN / 128, 3), 256>>>(nullptr);

    attn_h<<<dim3(S_LEN / 64, NH), 128>>>();

    gemm_h<0><<<dim3(DM / 128, S_LEN / 128, 1), 256>>>(out);
}

// round 17
// speedup vs baseline: 1.1260x; 1.0183x over previous
#include <cuda_runtime.h>
#include <cuda_fp16.h>
#include <cstdint>

#define S_LEN 4096
#define DM 1024
#define NH 16
#define HD 64
#define NEG_INF __int_as_float(0xff800000)
#define ONES2 0x3C003C00u   // half2 {1.0, 1.0}

// Scratch (device globals: allocation-free per harness rules). All fp16.
__device__ __half g_Q[NH * S_LEN * HD];  // [h][s][d], pre-scaled 0.125*log2(e)
__device__ __half g_K[NH * S_LEN * HD];
__device__ __half g_V[NH * S_LEN * HD];
__device__ __half g_O[S_LEN * DM];       // [s][h*64+d]
__device__ __half g_Xr[S_LEN * DM];      // x in fp16
__device__ __half g_Wr[4][DM * DM];      // W^T: [n][k], k contiguous

__device__ __forceinline__ void mma_f16(float& d0, float& d1, float& d2, float& d3,
                                        unsigned a0, unsigned a1, unsigned a2, unsigned a3,
                                        unsigned b0, unsigned b1) {
    asm volatile(
        "mma.sync.aligned.m16n8k16.row.col.f32.f16.f16.f32 "
        "{%0,%1,%2,%3}, {%4,%5,%6,%7}, {%8,%9}, {%0,%1,%2,%3};"
        : "+f"(d0), "+f"(d1), "+f"(d2), "+f"(d3)
        : "r"(a0), "r"(a1), "r"(a2), "r"(a3), "r"(b0), "r"(b1));
}

__device__ __forceinline__ void ldm_x4(unsigned& r0, unsigned& r1, unsigned& r2,
                                       unsigned& r3, unsigned addr) {
    asm volatile("ldmatrix.sync.aligned.m8n8.x4.shared.b16 {%0,%1,%2,%3}, [%4];"
                 : "=r"(r0), "=r"(r1), "=r"(r2), "=r"(r3) : "r"(addr));
}

__device__ __forceinline__ void cp16(void* smem_dst, const void* gsrc) {
    unsigned d = (unsigned)__cvta_generic_to_shared(smem_dst);
    asm volatile("cp.async.cg.shared.global [%0], [%1], 16;" :: "r"(d), "l"(gsrc));
}
__device__ __forceinline__ void cp16s(unsigned smem_addr, const void* gsrc) {
    asm volatile("cp.async.cg.shared.global [%0], [%1], 16;"
                 :: "r"(smem_addr), "l"(gsrc));
}
__device__ __forceinline__ void cp_commit() { asm volatile("cp.async.commit_group;"); }
template <int N>
__device__ __forceinline__ void cp_wait() {
    asm volatile("cp.async.wait_group %0;" :: "n"(N));
}

__device__ __forceinline__ unsigned pack2(float a, float b) {
    __half2 h = __floats2half2_rn(a, b);
    return *(unsigned*)&h;
}

// ---------------------------------------------------------------------------
// Prepass A: x -> fp16.
// ---------------------------------------------------------------------------
__global__ __launch_bounds__(256) void prepass_x(const float* __restrict__ x) {
    int i = blockIdx.x * 256 + threadIdx.x;
    float4 v = ((const float4*)x)[i];
    uint2 o;
    o.x = pack2(v.x, v.y);
    o.y = pack2(v.z, v.w);
    ((uint2*)g_Xr)[i] = o;
}

// ---------------------------------------------------------------------------
// Prepass B: transpose + fp16: g_Wr[w][n][k] = W[k][n].
// ---------------------------------------------------------------------------
__global__ __launch_bounds__(256) void prepass_w(const float* __restrict__ wq,
                                                 const float* __restrict__ wk,
                                                 const float* __restrict__ wv,
                                                 const float* __restrict__ wo) {
    __shared__ float t[32][33];
    const int w = blockIdx.z;
    const float* W = (w == 0) ? wq : (w == 1) ? wk : (w == 2) ? wv : wo;
    __half* D = g_Wr[w];
    const int k0 = blockIdx.y * 32, n0 = blockIdx.x * 32;
    const int tx = threadIdx.x & 31, ty = threadIdx.x >> 5;
#pragma unroll
    for (int j = 0; j < 4; j++)
        t[ty + 8 * j][tx] = W[(k0 + ty + 8 * j) * DM + n0 + tx];
    __syncthreads();
#pragma unroll
    for (int j = 0; j < 4; j++)
        D[(n0 + ty + 8 * j) * DM + k0 + tx] = __float2half_rn(t[tx][ty + 8 * j]);
}

// ---------------------------------------------------------------------------
// fp16 tensor-core GEMM (R12 configuration — measured best).
// Tile 128x128, BK=32, cp.async double-buffered, SINGLE barrier/iter.
// Fragments via ldmatrix.x4 (A: 4, B: 2 per kt). Static smem ~40 KB.
// ---------------------------------------------------------------------------
#define GSTR 40   // halves per row (32+8): 80B stride = 5x16B (cp.async-OK)

template <int MODE>
__global__ __launch_bounds__(256) void gemm_h(float* __restrict__ Cp) {
    __shared__ __align__(16) __half As[2][128 * GSTR];
    __shared__ __align__(16) __half Bs[2][128 * GSTR];

    const int tid = threadIdx.x;
    const int lane = tid & 31, wid = tid >> 5;
    const int g = lane >> 2, t = lane & 3;
    const int wm = wid & 1, wn = wid >> 1;
    const int row0 = blockIdx.y * 128;
    const int col0 = blockIdx.x * 128;
    const int z = (MODE == 0) ? 3 : blockIdx.z;

    const __half* A = (MODE == 0) ? (const __half*)g_O : (const __half*)g_Xr;
    const __half* B = g_Wr[z];

    // ldmatrix lane roles
    const int lr = lane & 7, quad = lane >> 3;
    const int arow = lr + (quad & 1) * 8;
    const int acol = (quad >> 1) * 8;
    const int brow = lr + (quad >> 1) * 8;
    const int bcol = (quad & 1) * 8;

    unsigned asb[2], bsb[2];
#pragma unroll
    for (int b = 0; b < 2; b++) {
        asb[b] = (unsigned)__cvta_generic_to_shared(&As[b][0]);
        bsb[b] = (unsigned)__cvta_generic_to_shared(&Bs[b][0]);
    }

    float acc[4][4][4] = {};

#define LOADT(k0, buf)                                                        \
    do {                                                                      \
        _Pragma("unroll")                                                     \
        for (int j = 0; j < 2; j++) {                                         \
            const int s = tid + j * 256;                                      \
            const int r = s >> 2, c = (s & 3) * 8;                            \
            cp16(&As[buf][r * GSTR + c], &A[(row0 + r) * DM + (k0) + c]);     \
            cp16(&Bs[buf][r * GSTR + c], &B[(col0 + r) * DM + (k0) + c]);     \
        }                                                                     \
        cp_commit();                                                          \
    } while (0)

    LOADT(0, 0);

    for (int it = 0; it < DM / 32; it++) {
        const int buf = it & 1;
        cp_wait<0>();        // own copies of tile `it` done
        __syncthreads();     // all copies visible; prior-iter reads done
        if (it + 1 < DM / 32) LOADT((it + 1) * 32, buf ^ 1);

#pragma unroll
        for (int kt = 0; kt < 2; kt++) {
            const int kk = kt * 16;
            unsigned a[4][4], b[4][2];
#pragma unroll
            for (int mi = 0; mi < 4; mi++)
                ldm_x4(a[mi][0], a[mi][1], a[mi][2], a[mi][3],
                       asb[buf] + ((wm * 64 + mi * 16 + arow) * GSTR + kk + acol) * 2);
#pragma unroll
            for (int pr = 0; pr < 2; pr++)
                ldm_x4(b[2 * pr][0], b[2 * pr][1], b[2 * pr + 1][0], b[2 * pr + 1][1],
                       bsb[buf] + ((wn * 32 + pr * 16 + brow) * GSTR + kk + bcol) * 2);
#pragma unroll
            for (int mi = 0; mi < 4; mi++)
#pragma unroll
                for (int ni = 0; ni < 4; ni++)
                    mma_f16(acc[mi][ni][0], acc[mi][ni][1], acc[mi][ni][2], acc[mi][ni][3],
                            a[mi][0], a[mi][1], a[mi][2], a[mi][3],
                            b[ni][0], b[ni][1]);
        }
    }
#undef LOADT

    if (MODE == 0) {
#pragma unroll
        for (int mi = 0; mi < 4; mi++) {
            const int r0 = row0 + wm * 64 + mi * 16 + g;
#pragma unroll
            for (int ni = 0; ni < 4; ni++) {
                const int c = col0 + wn * 32 + ni * 8 + 2 * t;
                *(float2*)&Cp[r0 * DM + c] = make_float2(acc[mi][ni][0], acc[mi][ni][1]);
                *(float2*)&Cp[(r0 + 8) * DM + c] = make_float2(acc[mi][ni][2], acc[mi][ni][3]);
            }
        }
    } else {
        __half* C = (z == 0) ? g_Q : (z == 1) ? g_K : g_V;
        // Q: fold 1/sqrt(64) and log2(e) so softmax runs in exp2 domain.
        const float sc = (z == 0) ? 0.125f * 1.4426950408889634f : 1.0f;
#pragma unroll
        for (int mi = 0; mi < 4; mi++) {
            const int r0 = row0 + wm * 64 + mi * 16 + g;
#pragma unroll
            for (int ni = 0; ni < 4; ni++) {
                const int c = col0 + wn * 32 + ni * 8 + 2 * t;
                const int hh = c >> 6, d = c & 63;
                __half* dst = &C[hh * (S_LEN * HD) + r0 * HD + d];
                *(unsigned*)dst = pack2(acc[mi][ni][0] * sc, acc[mi][ni][1] * sc);
                *(unsigned*)(dst + 8 * HD) = pack2(acc[mi][ni][2] * sc, acc[mi][ni][3] * sc);
            }
        }
    }
}

// ---------------------------------------------------------------------------
// Flash attention, fp16 mma, causal. Br=64, Bc=64, 4 warps, 4 CTAs/SM.
// THREE-stage cp.async pipeline (lookahead-2): tile kb+2 issued each iter,
// cp_wait<1> leaves the newest group in flight -> the needed tile has had
// two full iterations to land. Dynamic smem 55.3 KB (3 bufs x (K+V)).
// Per-warp compute identical to R16.
// ---------------------------------------------------------------------------
#define KVS 72                         // halves per row: 144B = 9x16B
#define TILE_H (64 * KVS)              // halves per tile
#define TILE_B (TILE_H * 2)            // 9216 bytes per tile
#define ATT_SMEM (6 * TILE_B)          // 3 K tiles + 3 V tiles = 55296 B

__global__ __launch_bounds__(128, 4) void attn_h() {
    extern __shared__ __align__(16) char smraw[];
    __half* Ksm = (__half*)smraw;                      // [3][TILE_H]
    __half* Vsm = (__half*)(smraw + 3 * TILE_B);       // [3][TILE_H]

    const int qb = (int)gridDim.x - 1 - (int)blockIdx.x;  // long CTAs first
    const int h  = blockIdx.y;
    const int tid = threadIdx.x;
    const int lane = tid & 31, wid = tid >> 5;
    const int g = lane >> 2, t = lane & 3;
    const int wm = wid;                   // 0..3 -> 16-row stripe

    const __half* Qh = g_Q + h * (S_LEN * HD);
    const __half* Kh = g_K + h * (S_LEN * HD);
    const __half* Vh = g_V + h * (S_LEN * HD);

    const unsigned ksb = (unsigned)__cvta_generic_to_shared(Ksm);
    const unsigned vsb = (unsigned)__cvta_generic_to_shared(Vsm);

    const int kb_end = qb;                // inclusive; 64-col kv blocks

    // 64 rows x 64 halves = 512 16B-segs per matrix; 4 K + 4 V per thread.
#define LOAD_KV(kb, bi)                                                       \
    do {                                                                      \
        const unsigned ko = ksb + (bi) * TILE_B;                              \
        const unsigned vo = vsb + (bi) * TILE_B;                              \
        _Pragma("unroll")                                                     \
        for (int j = 0; j < 4; j++) {                                         \
            const int s = tid + j * 128;                                      \
            const int r = s >> 3, c = (s & 7) * 8;                            \
            cp16s(ko + (r * KVS + c) * 2, &Kh[((kb) * 64 + r) * HD + c]);     \
            cp16s(vo + (r * KVS + c) * 2, &Vh[((kb) * 64 + r) * HD + c]);     \
        }                                                                     \
        cp_commit();                                                          \
    } while (0)

    LOAD_KV(0, 0);
    LOAD_KV(1, 1);   // always in-bounds (rows <= 127 < S_LEN); unused if qb==0

    // Q fragments in registers (4 k16 blocks), rows qb*64 + wm*16 + {g, g+8}.
    unsigned qf[4][4];
    {
        const int q0 = qb * 64 + wm * 16 + g;
#pragma unroll
        for (int kt = 0; kt < 4; kt++) {
            const int kk = kt * 16;
            qf[kt][0] = *(const unsigned*)&Qh[q0 * HD + kk + 2 * t];
            qf[kt][1] = *(const unsigned*)&Qh[(q0 + 8) * HD + kk + 2 * t];
            qf[kt][2] = *(const unsigned*)&Qh[q0 * HD + kk + 2 * t + 8];
            qf[kt][3] = *(const unsigned*)&Qh[(q0 + 8) * HD + kk + 2 * t + 8];
        }
    }

    // ldmatrix.trans lane offsets for V
    const int lr = lane & 7, quad = lane >> 3;
    const int vrow = lr + (quad & 1) * 8;
    const int vcol = (quad >> 1) * 8;

    float m0 = NEG_INF, m1 = NEG_INF;
    float lac[4] = {};                    // row-sum accumulators (ones-MMA)
    float o[8][4] = {};

    int cur = 0, n2 = 2;                  // buffer of tile kb / tile kb+2
    for (int kb = 0; kb <= kb_end; kb++) {
        cp_wait<1>();       // tile kb complete (kb+1 may be in flight)
        __syncthreads();    // copies visible; prior-iter reads of buf n2 done
        if (kb + 2 <= kb_end) LOAD_KV(kb + 2, n2);
        else cp_commit();   // empty group keeps wait_group counting consistent

        const __half* Kt = Ksm + cur * TILE_H;
        const unsigned vbase = vsb + cur * TILE_B;

        // ---- S = Q K^T : 16 rows x 64 cols per warp (scalar-LDS K frags) ----
        float s[8][4] = {};
#pragma unroll
        for (int kt = 0; kt < 4; kt++) {
            const int kk = kt * 16;
#pragma unroll
            for (int ni = 0; ni < 8; ni++) {
                const __half* bb = &Kt[(ni * 8 + g) * KVS + kk];
                mma_f16(s[ni][0], s[ni][1], s[ni][2], s[ni][3],
                        qf[kt][0], qf[kt][1], qf[kt][2], qf[kt][3],
                        *(const unsigned*)&bb[2 * t],
                        *(const unsigned*)&bb[2 * t + 8]);
            }
        }

        // ---- causal mask (diagonal block kb == qb only) ----
        if (kb >= qb) {
            const int rg0 = qb * 64 + wm * 16 + g;
            const int rg1 = rg0 + 8;
#pragma unroll
            for (int ni = 0; ni < 8; ni++) {
                const int cb = kb * 64 + ni * 8 + 2 * t;
                if (cb > rg0) s[ni][0] = NEG_INF;
                if (cb + 1 > rg0) s[ni][1] = NEG_INF;
                if (cb > rg1) s[ni][2] = NEG_INF;
                if (cb + 1 > rg1) s[ni][3] = NEG_INF;
            }
        }

        // ---- online max (warp-local, exp2 domain) ----
        float pm0 = fmaxf(s[0][0], s[0][1]);
        float pm1 = fmaxf(s[0][2], s[0][3]);
#pragma unroll
        for (int ni = 1; ni < 8; ni++) {
            pm0 = fmaxf(pm0, fmaxf(s[ni][0], s[ni][1]));
            pm1 = fmaxf(pm1, fmaxf(s[ni][2], s[ni][3]));
        }
#pragma unroll
        for (int off = 1; off < 4; off <<= 1) {
            pm0 = fmaxf(pm0, __shfl_xor_sync(0xffffffffu, pm0, off, 4));
            pm1 = fmaxf(pm1, __shfl_xor_sync(0xffffffffu, pm1, off, 4));
        }
        const float mx0 = fmaxf(m0, pm0);
        const float mx1 = fmaxf(m1, pm1);
        const float scl0 = exp2f(m0 - mx0);
        const float scl1 = exp2f(m1 - mx1);
        m0 = mx0; m1 = mx1;

        // ---- P = 2^(S-m) in fp16x2; packed regs ARE the PV A-fragments ----
        unsigned pp[8][2];
#pragma unroll
        for (int ni = 0; ni < 8; ni++) {
            unsigned e0 = pack2(s[ni][0] - mx0, s[ni][1] - mx0);
            unsigned e1 = pack2(s[ni][2] - mx1, s[ni][3] - mx1);
            asm("ex2.approx.f16x2 %0, %0;" : "+r"(e0));
            asm("ex2.approx.f16x2 %0, %0;" : "+r"(e1));
            pp[ni][0] = e0;
            pp[ni][1] = e1;
        }

        // ---- rescale accumulators ----
        lac[0] *= scl0; lac[1] *= scl0; lac[2] *= scl1; lac[3] *= scl1;
#pragma unroll
        for (int ni = 0; ni < 8; ni++) {
            o[ni][0] *= scl0; o[ni][1] *= scl0;
            o[ni][2] *= scl1; o[ni][3] *= scl1;
        }

        // ---- l += P @ 1 (ones-MMA, fp32 accum, consistent with PV's P) ----
#pragma unroll
        for (int jp = 0; jp < 4; jp++)
            mma_f16(lac[0], lac[1], lac[2], lac[3],
                    pp[2 * jp][0], pp[2 * jp][1],
                    pp[2 * jp + 1][0], pp[2 * jp + 1][1],
                    ONES2, ONES2);

        // ---- O += P V (ldmatrix.trans) ----
#pragma unroll
        for (int jp = 0; jp < 4; jp++) {
            const unsigned pa0 = pp[2 * jp][0], pa1 = pp[2 * jp][1];
            const unsigned pa2 = pp[2 * jp + 1][0], pa3 = pp[2 * jp + 1][1];
#pragma unroll
            for (int np = 0; np < 4; np++) {
                unsigned v0, v1, v2, v3;
                unsigned addr = vbase + ((jp * 16 + vrow) * KVS + np * 16 + vcol) * 2;
                asm volatile(
                    "ldmatrix.sync.aligned.m8n8.x4.trans.shared.b16 "
                    "{%0,%1,%2,%3}, [%4];"
                    : "=r"(v0), "=r"(v1), "=r"(v2), "=r"(v3) : "r"(addr));
                mma_f16(o[np * 2][0], o[np * 2][1], o[np * 2][2], o[np * 2][3],
                        pa0, pa1, pa2, pa3, v0, v1);
                mma_f16(o[np * 2 + 1][0], o[np * 2 + 1][1],
                        o[np * 2 + 1][2], o[np * 2 + 1][3],
                        pa0, pa1, pa2, pa3, v2, v3);
            }
        }

        cur = (cur == 2) ? 0 : cur + 1;
        n2  = (n2 == 2) ? 0 : n2 + 1;
    }
#undef LOAD_KV

    {
        const float inv0 = 1.0f / lac[0];
        const float inv1 = 1.0f / lac[2];
        const int q0 = qb * 64 + wm * 16 + g;
#pragma unroll
        for (int ni = 0; ni < 8; ni++) {
            const int c = h * HD + ni * 8 + 2 * t;
            *(unsigned*)&g_O[q0 * DM + c] = pack2(o[ni][0] * inv0, o[ni][1] * inv0);
            *(unsigned*)&g_O[(q0 + 8) * DM + c] = pack2(o[ni][2] * inv1, o[ni][3] * inv1);
        }
    }
}

// ---------------------------------------------------------------------------
extern "C" void kernel_launch(void* const* d_in, const int* in_sizes, int n_in,
                              void* d_out, int out_size) {
    (void)in_sizes; (void)n_in; (void)out_size;
    const float* x  = (const float*)d_in[0];
    const float* Wq = (const float*)d_in[1];
    const float* Wk = (const float*)d_in[2];
    const float* Wv = (const float*)d_in[3];
    const float* Wo = (const float*)d_in[4];
    float* out = (float*)d_out;

    cudaFuncSetAttribute(attn_h, cudaFuncAttributeMaxDynamicSharedMemorySize,
                         ATT_SMEM);

    prepass_x<<<S_LEN * DM / 4 / 256, 256>>>(x);
    prepass_w<<<dim3(DM / 32, DM / 32, 4), 256>>>(Wq, Wk, Wv, Wo);

    gemm_h<1><<<dim3(DM / 128, S_LEN / 128, 3), 256>>>(nullptr);

    attn_h<<<dim3(S_LEN / 64, NH), 128, ATT_SMEM>>>();

    gemm_h<0><<<dim3(DM / 128, S_LEN / 128, 1), 256>>>(out);
}